// round 3
// baseline (speedup 1.0000x reference)
#include <cuda_runtime.h>
#include <stdint.h>
#include <float.h>

// Shapes: data [64,1024,256] f32, locs [64,256,2] f32, out [64,1024,2500] f32
#define B_  64
#define T_  1024
#define N_  256
#define G_  50
#define GG  2500
#define TPB 256
#define T_PER_BLOCK 32
#define R_  8              // t-rows per barrier window
#define NCH 8              // FMNMX chains in phase A

__device__ uint8_t g_nearest[B_ * GG];

// ---------------------------------------------------------------------------
// Kernel A: argmin over 256 sensors of sqrt(dx^2+dy^2), bit-exact vs jnp:
//  Phase A: branchless exact min m of d2 (8 independent FMNMX chains).
//  Phase B: first index whose __fsqrt_rn(d2)==__fsqrt_rn(m). The prefilter
//           d2<=m*(1+2e-6) conservatively covers the sqrt rounding class
//           (width <= ~2.4e-7*m), so no candidate is missed; answer is the
//           minimum matching j => first-index-wins, matching jnp.argmin.
//  d2 built with explicit rn mul/add (no FMA contraction), identical in both
//  phases, matching XLA's rounding.
// ---------------------------------------------------------------------------
__global__ void nearest_kernel(const float* __restrict__ locs) {
    __shared__ float2 sloc[N_];
    const int b = blockIdx.y;
    const int tid = threadIdx.x;

    {
        float2 l = reinterpret_cast<const float2*>(locs)[b * N_ + tid];
        sloc[tid].x = __fadd_rn(__fmul_rn(l.x, 25.0f), 25.0f);
        sloc[tid].y = __fadd_rn(__fmul_rn(l.y, 25.0f), 25.0f);
    }
    __syncthreads();

    const int g = blockIdx.x * blockDim.x + tid;
    if (g >= GG) return;

    const float gx = (float)(g / G_);
    const float gy = (float)(g % G_);

    // Phase A: branchless exact min of d2
    float m[NCH];
    #pragma unroll
    for (int c = 0; c < NCH; ++c) m[c] = FLT_MAX;

    #pragma unroll 4
    for (int i = 0; i < N_ / NCH; ++i) {
        #pragma unroll
        for (int c = 0; c < NCH; ++c) {
            int j = i * NCH + c;
            float dx = __fsub_rn(sloc[j].x, gx);
            float dy = __fsub_rn(sloc[j].y, gy);
            float d2 = __fadd_rn(__fmul_rn(dx, dx), __fmul_rn(dy, dy));
            m[c] = fminf(m[c], d2);
        }
    }
    float mm = m[0];
    #pragma unroll
    for (int c = 1; c < NCH; ++c) mm = fminf(mm, m[c]);

    const float s      = __fsqrt_rn(mm);
    const float thresh = __fmul_rn(mm, 1.000002f);   // covers sqrt tie class

    // Phase B: min index whose sqrt matches s (branch taken ~1/256 per lane)
    int bi = N_ - 1;
    #pragma unroll 8
    for (int j = 0; j < N_; ++j) {
        float dx = __fsub_rn(sloc[j].x, gx);
        float dy = __fsub_rn(sloc[j].y, gy);
        float d2 = __fadd_rn(__fmul_rn(dx, dx), __fmul_rn(dy, dy));
        if (d2 <= thresh) {                    // rare
            if (__fsqrt_rn(d2) == s) bi = min(bi, j);
        }
    }
    g_nearest[b * GG + g] = (uint8_t)bi;
}

// ---------------------------------------------------------------------------
// Kernel B: out[b,t,g] = data[b,t, nearest[b,g]]
// 8 t-rows staged per barrier window in two transposed float4 caches; each
// thread issues 24 independent STG.128 per window for deep store MLP.
// ---------------------------------------------------------------------------
__global__ __launch_bounds__(TPB)
void gather_kernel(const float* __restrict__ data, float* __restrict__ out) {
    __shared__ float4  rowsA[N_];     // t-rows 0..3 of window (sensor-major)
    __shared__ float4  rowsB[N_];     // t-rows 4..7
    __shared__ uint8_t sidx[GG];

    const int b   = blockIdx.y;
    const int tid = threadIdx.x;

    {
        const uint32_t* src = reinterpret_cast<const uint32_t*>(g_nearest + (size_t)b * GG);
        uint32_t* dst = reinterpret_cast<uint32_t*>(sidx);
        #pragma unroll
        for (int k = tid; k < GG / 4; k += TPB) dst[k] = src[k];
    }
    __syncthreads();

    int idx[3][4];
    #pragma unroll
    for (int gi = 0; gi < 3; ++gi) {
        int k = tid + gi * TPB;
        if (k < GG / 4) {
            idx[gi][0] = sidx[4 * k + 0];
            idx[gi][1] = sidx[4 * k + 1];
            idx[gi][2] = sidx[4 * k + 2];
            idx[gi][3] = sidx[4 * k + 3];
        }
    }

    const int t0 = blockIdx.x * T_PER_BLOCK;
    const float* dbase = data + ((size_t)b * T_ + t0) * (size_t)N_;
    float*       obase = out  + ((size_t)b * T_ + t0) * (size_t)GG;

    #pragma unroll 1
    for (int w = 0; w < T_PER_BLOCK / R_; ++w) {
        __syncthreads();
        {
            const float* d0 = dbase + (size_t)(w * R_) * N_ + tid;
            float4 va, vb;
            va.x = __ldcs(d0 + 0 * N_);
            va.y = __ldcs(d0 + 1 * N_);
            va.z = __ldcs(d0 + 2 * N_);
            va.w = __ldcs(d0 + 3 * N_);
            vb.x = __ldcs(d0 + 4 * N_);
            vb.y = __ldcs(d0 + 5 * N_);
            vb.z = __ldcs(d0 + 6 * N_);
            vb.w = __ldcs(d0 + 7 * N_);
            rowsA[tid] = va;
            rowsB[tid] = vb;
        }
        __syncthreads();

        float* o = obase + (size_t)(w * R_) * GG;
        #pragma unroll
        for (int gi = 0; gi < 3; ++gi) {
            int k = tid + gi * TPB;
            if (k < GG / 4) {
                float4 a0 = rowsA[idx[gi][0]];
                float4 a1 = rowsA[idx[gi][1]];
                float4 a2 = rowsA[idx[gi][2]];
                float4 a3 = rowsA[idx[gi][3]];
                __stcs(reinterpret_cast<float4*>(o + 0 * GG) + k,
                       make_float4(a0.x, a1.x, a2.x, a3.x));
                __stcs(reinterpret_cast<float4*>(o + 1 * GG) + k,
                       make_float4(a0.y, a1.y, a2.y, a3.y));
                __stcs(reinterpret_cast<float4*>(o + 2 * GG) + k,
                       make_float4(a0.z, a1.z, a2.z, a3.z));
                __stcs(reinterpret_cast<float4*>(o + 3 * GG) + k,
                       make_float4(a0.w, a1.w, a2.w, a3.w));
                float4 b0 = rowsB[idx[gi][0]];
                float4 b1 = rowsB[idx[gi][1]];
                float4 b2 = rowsB[idx[gi][2]];
                float4 b3 = rowsB[idx[gi][3]];
                __stcs(reinterpret_cast<float4*>(o + 4 * GG) + k,
                       make_float4(b0.x, b1.x, b2.x, b3.x));
                __stcs(reinterpret_cast<float4*>(o + 5 * GG) + k,
                       make_float4(b0.y, b1.y, b2.y, b3.y));
                __stcs(reinterpret_cast<float4*>(o + 6 * GG) + k,
                       make_float4(b0.z, b1.z, b2.z, b3.z));
                __stcs(reinterpret_cast<float4*>(o + 7 * GG) + k,
                       make_float4(b0.w, b1.w, b2.w, b3.w));
            }
        }
    }
}

// ---------------------------------------------------------------------------
extern "C" void kernel_launch(void* const* d_in, const int* in_sizes, int n_in,
                              void* d_out, int out_size) {
    const float* data = (const float*)d_in[0];
    const float* locs = (const float*)d_in[1];
    if (n_in >= 2 && in_sizes[0] < in_sizes[1]) {
        data = (const float*)d_in[1];
        locs = (const float*)d_in[0];
    }
    float* out = (float*)d_out;

    dim3 gridA((GG + TPB - 1) / TPB, B_);
    nearest_kernel<<<gridA, TPB>>>(locs);

    dim3 gridB(T_ / T_PER_BLOCK, B_);
    gather_kernel<<<gridB, TPB>>>(data, out);
}